// round 1
// baseline (speedup 1.0000x reference)
#include <cuda_runtime.h>
#include <cuda_bf16.h>
#include <math.h>

#define N_NODES 50000
#define N_EDGES 600000
#define LATENT  128
#define IN_FEAT 7
#define STEPS   3

// ---------------- scratch (no allocations allowed) ----------------
__device__ float g_h   [N_NODES * LATENT];
__device__ float g_x1  [N_NODES * LATENT];
__device__ float g_x2  [N_NODES * LATENT];
__device__ float g_agg [N_NODES * LATENT];
__device__ float g_degs[N_NODES];
__device__ float g_degr[N_NODES];
__device__ float g_invs[N_NODES];
__device__ float g_invr[N_NODES];

// ---------------- degree / normalization ----------------
__global__ void degree_kernel(const int* __restrict__ senders,
                              const int* __restrict__ receivers) {
    int e = blockIdx.x * blockDim.x + threadIdx.x;
    if (e >= N_EDGES) return;
    atomicAdd(&g_degs[senders[e]],   1.0f);
    atomicAdd(&g_degr[receivers[e]], 1.0f);
}

__global__ void invsqrt_kernel() {
    int i = blockIdx.x * blockDim.x + threadIdx.x;
    if (i >= N_NODES) return;
    g_invs[i] = rsqrtf(fmaxf(g_degs[i], 1.0f));
    g_invr[i] = rsqrtf(fmaxf(g_degr[i], 1.0f));
}

// ---------------- embed: h = nodes @ W_embed + b ----------------
__global__ void embed_kernel(const float* __restrict__ nodes,
                             const float* __restrict__ We,
                             const float* __restrict__ be) {
    int idx = blockIdx.x * blockDim.x + threadIdx.x;
    if (idx >= N_NODES * LATENT) return;
    int n = idx >> 7, c = idx & 127;
    float acc = be[c];
#pragma unroll
    for (int k = 0; k < IN_FEAT; k++)
        acc = fmaf(nodes[n * IN_FEAT + k], We[k * LATENT + c], acc);
    g_h[idx] = acc;
}

// ---------------- generic 128-wide SGEMM ----------------
// C[N,128] = relu?(A[N,128] @ W[128,128] + bias) * (rowscale ? rowscale[row] : 1)
#define BM 128
#define BK 16
__global__ __launch_bounds__(256, 2)
void gemm128_kernel(const float* __restrict__ A,
                    const float* __restrict__ W,
                    const float* __restrict__ bias,
                    const float* __restrict__ rowscale,
                    float* __restrict__ C, int N, int relu) {
    __shared__ float As[BK][BM];
    __shared__ float Ws[BK][LATENT];

    int t  = threadIdx.x;
    int tx = t & 15;        // col group
    int ty = t >> 4;        // row group
    int row0 = blockIdx.x * BM;

    float acc[8][8];
#pragma unroll
    for (int i = 0; i < 8; i++)
#pragma unroll
        for (int j = 0; j < 8; j++) acc[i][j] = 0.0f;

    for (int kk = 0; kk < LATENT; kk += BK) {
        // load W chunk [BK][128]: 512 float4, 2 per thread, coalesced
#pragma unroll
        for (int j = 0; j < 2; j++) {
            int v  = t + j * 256;      // 0..511
            int k  = v >> 5;           // 16 k-rows
            int c4 = v & 31;           // 32 float4 per row
            float4 w = *(const float4*)&W[(kk + k) * LATENT + c4 * 4];
            *(float4*)&Ws[k][c4 * 4] = w;
        }
        // load A chunk [128 rows][BK], store transposed As[k][row]
#pragma unroll
        for (int j = 0; j < 2; j++) {
            int v = t + j * 256;       // 0..511
            int r = v >> 2;            // 128 rows
            int q = v & 3;             // 4 float4 per row
            float4 a;
            int grow = row0 + r;
            if (grow < N) a = *(const float4*)&A[grow * LATENT + kk + q * 4];
            else          a = make_float4(0.f, 0.f, 0.f, 0.f);
            As[q * 4 + 0][r] = a.x;
            As[q * 4 + 1][r] = a.y;
            As[q * 4 + 2][r] = a.z;
            As[q * 4 + 3][r] = a.w;
        }
        __syncthreads();
#pragma unroll
        for (int k = 0; k < BK; k++) {
            float4 a0 = *(const float4*)&As[k][ty * 8];
            float4 a1 = *(const float4*)&As[k][ty * 8 + 4];
            float4 b0 = *(const float4*)&Ws[k][tx * 8];
            float4 b1 = *(const float4*)&Ws[k][tx * 8 + 4];
            float a[8] = {a0.x, a0.y, a0.z, a0.w, a1.x, a1.y, a1.z, a1.w};
            float b[8] = {b0.x, b0.y, b0.z, b0.w, b1.x, b1.y, b1.z, b1.w};
#pragma unroll
            for (int i = 0; i < 8; i++)
#pragma unroll
                for (int j = 0; j < 8; j++)
                    acc[i][j] = fmaf(a[i], b[j], acc[i][j]);
        }
        __syncthreads();
    }

    // epilogue
    float bs[8];
#pragma unroll
    for (int j = 0; j < 8; j++) bs[j] = bias[tx * 8 + j];
#pragma unroll
    for (int i = 0; i < 8; i++) {
        int r = row0 + ty * 8 + i;
        if (r >= N) continue;
        float rs = rowscale ? rowscale[r] : 1.0f;
        float out[8];
#pragma unroll
        for (int j = 0; j < 8; j++) {
            float c = acc[i][j] + bs[j];
            if (relu) c = fmaxf(c, 0.0f);
            out[j] = c * rs;
        }
        *(float4*)&C[r * LATENT + tx * 8]     = make_float4(out[0], out[1], out[2], out[3]);
        *(float4*)&C[r * LATENT + tx * 8 + 4] = make_float4(out[4], out[5], out[6], out[7]);
    }
}

// ---------------- scatter: agg[recv] += x2[send] ----------------
__global__ void scatter_kernel(const int* __restrict__ senders,
                               const int* __restrict__ receivers) {
    long long idx = (long long)blockIdx.x * blockDim.x + threadIdx.x;
    if (idx >= (long long)N_EDGES * 32) return;
    int e = (int)(idx >> 5);
    int g = (int)(idx & 31);
    int s = senders[e];
    int r = receivers[e];
    float4 v = *(const float4*)&g_x2[s * LATENT + g * 4];
    float* dst = &g_agg[r * LATENT + g * 4];
    atomicAdd(dst + 0, v.x);
    atomicAdd(dst + 1, v.y);
    atomicAdd(dst + 2, v.z);
    atomicAdd(dst + 3, v.w);
}

// ---------------- skip + layernorm (warp per node), in-place on g_h ----------------
__global__ void ln_kernel(const float* __restrict__ scale,
                          const float* __restrict__ bias) {
    int gid  = blockIdx.x * blockDim.x + threadIdx.x;
    int n    = gid >> 5;
    int lane = gid & 31;
    if (n >= N_NODES) return;
    float ir = g_invr[n];
    float4 hv = *(const float4*)&g_h[n * LATENT + lane * 4];
    float4 av = *(const float4*)&g_agg[n * LATENT + lane * 4];
    float v0 = hv.x + av.x * ir;
    float v1 = hv.y + av.y * ir;
    float v2 = hv.z + av.z * ir;
    float v3 = hv.w + av.w * ir;
    float sum = v0 + v1 + v2 + v3;
    float sq  = v0 * v0 + v1 * v1 + v2 * v2 + v3 * v3;
#pragma unroll
    for (int o = 16; o > 0; o >>= 1) {
        sum += __shfl_xor_sync(0xFFFFFFFF, sum, o);
        sq  += __shfl_xor_sync(0xFFFFFFFF, sq,  o);
    }
    float mean = sum * (1.0f / LATENT);
    float var  = sq * (1.0f / LATENT) - mean * mean;
    float rstd = rsqrtf(var + 1e-6f);
    float4 sc = *(const float4*)&scale[lane * 4];
    float4 bi = *(const float4*)&bias[lane * 4];
    float4 o4;
    o4.x = (v0 - mean) * rstd * sc.x + bi.x;
    o4.y = (v1 - mean) * rstd * sc.y + bi.y;
    o4.z = (v2 - mean) * rstd * sc.z + bi.z;
    o4.w = (v3 - mean) * rstd * sc.w + bi.w;
    *(float4*)&g_h[n * LATENT + lane * 4] = o4;
}

// ---------------- decode: out = h @ W_dec + b_dec (warp per node) ----------------
__global__ void decode_kernel(const float* __restrict__ Wd,
                              const float* __restrict__ bd,
                              float* __restrict__ out) {
    int gid  = blockIdx.x * blockDim.x + threadIdx.x;
    int n    = gid >> 5;
    int lane = gid & 31;
    if (n >= N_NODES) return;
    float4 hv = *(const float4*)&g_h[n * LATENT + lane * 4];
    float h[4] = {hv.x, hv.y, hv.z, hv.w};
    float acc[IN_FEAT];
#pragma unroll
    for (int o = 0; o < IN_FEAT; o++) acc[o] = 0.0f;
#pragma unroll
    for (int q = 0; q < 4; q++) {
        int k = lane * 4 + q;
#pragma unroll
        for (int o = 0; o < IN_FEAT; o++)
            acc[o] = fmaf(h[q], Wd[k * IN_FEAT + o], acc[o]);
    }
#pragma unroll
    for (int o = 0; o < IN_FEAT; o++) {
#pragma unroll
        for (int off = 16; off > 0; off >>= 1)
            acc[o] += __shfl_xor_sync(0xFFFFFFFF, acc[o], off);
    }
    if (lane < IN_FEAT)
        out[n * IN_FEAT + lane] = acc[lane] + bd[lane];
}

// ---------------- host launch ----------------
extern "C" void kernel_launch(void* const* d_in, const int* in_sizes, int n_in,
                              void* d_out, int out_size) {
    const float* nodes     = (const float*)d_in[0];
    const int*   senders   = (const int*)  d_in[1];
    const int*   receivers = (const int*)  d_in[2];
    const float* W_embed   = (const float*)d_in[3];
    const float* b_embed   = (const float*)d_in[4];
    const float* mlp_W     = (const float*)d_in[5];   // [3,2,128,128]
    const float* mlp_b     = (const float*)d_in[6];   // [3,2,128]
    const float* ln_scale  = (const float*)d_in[7];   // [3,128]
    const float* ln_bias   = (const float*)d_in[8];   // [3,128]
    const float* W_dec     = (const float*)d_in[9];   // [128,7]
    const float* b_dec     = (const float*)d_in[10];  // [7]
    float* out = (float*)d_out;

    void *p_h, *p_x1, *p_x2, *p_agg, *p_degs, *p_degr, *p_invs, *p_invr;
    cudaGetSymbolAddress(&p_h,    g_h);
    cudaGetSymbolAddress(&p_x1,   g_x1);
    cudaGetSymbolAddress(&p_x2,   g_x2);
    cudaGetSymbolAddress(&p_agg,  g_agg);
    cudaGetSymbolAddress(&p_degs, g_degs);
    cudaGetSymbolAddress(&p_degr, g_degr);
    cudaGetSymbolAddress(&p_invs, g_invs);
    cudaGetSymbolAddress(&p_invr, g_invr);

    // degrees + normalization
    cudaMemsetAsync(p_degs, 0, N_NODES * sizeof(float), 0);
    cudaMemsetAsync(p_degr, 0, N_NODES * sizeof(float), 0);
    degree_kernel<<<(N_EDGES + 255) / 256, 256>>>(senders, receivers);
    invsqrt_kernel<<<(N_NODES + 255) / 256, 256>>>();

    // embed
    embed_kernel<<<(N_NODES * LATENT + 255) / 256, 256>>>(nodes, W_embed, b_embed);

    const int gemm_grid = (N_NODES + BM - 1) / BM;
    const long long sc_threads = (long long)N_EDGES * 32;
    const int sc_grid = (int)((sc_threads + 255) / 256);
    const int ln_grid = (N_NODES * 32 + 255) / 256;

    for (int step = 0; step < STEPS; step++) {
        const float* W0 = mlp_W + ((size_t)step * 2 + 0) * LATENT * LATENT;
        const float* W1 = mlp_W + ((size_t)step * 2 + 1) * LATENT * LATENT;
        const float* b0 = mlp_b + ((size_t)step * 2 + 0) * LATENT;
        const float* b1 = mlp_b + ((size_t)step * 2 + 1) * LATENT;

        gemm128_kernel<<<gemm_grid, 256>>>((const float*)p_h, W0, b0, nullptr,
                                           (float*)p_x1, N_NODES, 1);
        gemm128_kernel<<<gemm_grid, 256>>>((const float*)p_x1, W1, b1, (const float*)p_invs,
                                           (float*)p_x2, N_NODES, 1);
        cudaMemsetAsync(p_agg, 0, (size_t)N_NODES * LATENT * sizeof(float), 0);
        scatter_kernel<<<sc_grid, 256>>>(senders, receivers);
        ln_kernel<<<ln_grid, 256>>>(ln_scale + step * LATENT, ln_bias + step * LATENT);
    }

    decode_kernel<<<ln_grid, 256>>>(W_dec, b_dec, out);
}

// round 5
// speedup vs baseline: 1.2673x; 1.2673x over previous
#include <cuda_runtime.h>
#include <cuda_bf16.h>
#include <math.h>

#define N_NODES 50000
#define N_EDGES 600000
#define LATENT  128
#define IN_FEAT 7
#define STEPS   3

// ---------------- scratch (no allocations allowed) ----------------
__device__ float g_h   [N_NODES * LATENT];
__device__ float g_x1  [N_NODES * LATENT];
__device__ float g_x2  [N_NODES * LATENT];
__device__ float g_agg [N_NODES * LATENT];
__device__ float g_degs[N_NODES];
__device__ float g_degr[N_NODES];
__device__ float g_invs[N_NODES];
__device__ float g_invr[N_NODES];

// ---------------- degree / normalization ----------------
__global__ void degree_kernel(const int* __restrict__ senders,
                              const int* __restrict__ receivers) {
    int e = blockIdx.x * blockDim.x + threadIdx.x;
    if (e >= N_EDGES) return;
    atomicAdd(&g_degs[senders[e]],   1.0f);
    atomicAdd(&g_degr[receivers[e]], 1.0f);
}

__global__ void invsqrt_kernel() {
    int i = blockIdx.x * blockDim.x + threadIdx.x;
    if (i >= N_NODES) return;
    g_invs[i] = rsqrtf(fmaxf(g_degs[i], 1.0f));
    g_invr[i] = rsqrtf(fmaxf(g_degr[i], 1.0f));
}

// ---------------- embed: h = nodes @ W_embed + b ----------------
__global__ void embed_kernel(const float* __restrict__ nodes,
                             const float* __restrict__ We,
                             const float* __restrict__ be) {
    int idx = blockIdx.x * blockDim.x + threadIdx.x;
    if (idx >= N_NODES * LATENT) return;
    int n = idx >> 7, c = idx & 127;
    float acc = be[c];
#pragma unroll
    for (int k = 0; k < IN_FEAT; k++)
        acc = fmaf(nodes[n * IN_FEAT + k], We[k * LATENT + c], acc);
    g_h[idx] = acc;
}

// ---------------- double-buffered 128-wide SGEMM ----------------
// C[N,128] = relu(A[N,128] @ W[128,128] + bias) * (rowscale ? rowscale[row] : 1)
#define BM 128
#define BK 16
__global__ __launch_bounds__(256, 2)
void gemm128_kernel(const float* __restrict__ A,
                    const float* __restrict__ W,
                    const float* __restrict__ bias,
                    const float* __restrict__ rowscale,
                    float* __restrict__ C, int N, int relu) {
    __shared__ float As[2][BK][BM];
    __shared__ float Ws[2][BK][LATENT];

    int t  = threadIdx.x;
    int tx = t & 15;        // col group
    int ty = t >> 4;        // row group
    int row0 = blockIdx.x * BM;

    // per-thread load coordinates (same for every tile)
    const int wv0 = t, wv1 = t + 256;               // W: 512 float4 per tile
    const int wk0 = wv0 >> 5, wc0 = (wv0 & 31) * 4;
    const int wk1 = wv1 >> 5, wc1 = (wv1 & 31) * 4;
    const int av0 = t, av1 = t + 256;               // A: 512 float4 per tile
    const int ar0 = av0 >> 2, aq0 = (av0 & 3) * 4;
    const int ar1 = av1 >> 2, aq1 = (av1 & 3) * 4;
    const int grow0 = row0 + ar0, grow1 = row0 + ar1;

    float acc[8][8];
#pragma unroll
    for (int i = 0; i < 8; i++)
#pragma unroll
        for (int j = 0; j < 8; j++) acc[i][j] = 0.0f;

    // --- prologue: load tile kk=0 into buffer 0 ---
    float4 w0 = *(const float4*)&W[wk0 * LATENT + wc0];
    float4 w1 = *(const float4*)&W[wk1 * LATENT + wc1];
    float4 a0 = (grow0 < N) ? *(const float4*)&A[grow0 * LATENT + aq0]
                            : make_float4(0.f, 0.f, 0.f, 0.f);
    float4 a1 = (grow1 < N) ? *(const float4*)&A[grow1 * LATENT + aq1]
                            : make_float4(0.f, 0.f, 0.f, 0.f);
    *(float4*)&Ws[0][wk0][wc0] = w0;
    *(float4*)&Ws[0][wk1][wc1] = w1;
    As[0][aq0 + 0][ar0] = a0.x; As[0][aq0 + 1][ar0] = a0.y;
    As[0][aq0 + 2][ar0] = a0.z; As[0][aq0 + 3][ar0] = a0.w;
    As[0][aq1 + 0][ar1] = a1.x; As[0][aq1 + 1][ar1] = a1.y;
    As[0][aq1 + 2][ar1] = a1.z; As[0][aq1 + 3][ar1] = a1.w;
    __syncthreads();

#pragma unroll
    for (int it = 0; it < LATENT / BK; it++) {
        int cur = it & 1, nxt = cur ^ 1;
        int kk_next = (it + 1) * BK;
        // prefetch next tile into registers (overlaps with compute)
        if (kk_next < LATENT) {
            w0 = *(const float4*)&W[(kk_next + wk0) * LATENT + wc0];
            w1 = *(const float4*)&W[(kk_next + wk1) * LATENT + wc1];
            a0 = (grow0 < N) ? *(const float4*)&A[grow0 * LATENT + kk_next + aq0]
                             : make_float4(0.f, 0.f, 0.f, 0.f);
            a1 = (grow1 < N) ? *(const float4*)&A[grow1 * LATENT + kk_next + aq1]
                             : make_float4(0.f, 0.f, 0.f, 0.f);
        }
#pragma unroll
        for (int k = 0; k < BK; k++) {
            float4 av0_ = *(const float4*)&As[cur][k][ty * 8];
            float4 av1_ = *(const float4*)&As[cur][k][ty * 8 + 4];
            float4 bv0_ = *(const float4*)&Ws[cur][k][tx * 8];
            float4 bv1_ = *(const float4*)&Ws[cur][k][tx * 8 + 4];
            float a[8] = {av0_.x, av0_.y, av0_.z, av0_.w, av1_.x, av1_.y, av1_.z, av1_.w};
            float b[8] = {bv0_.x, bv0_.y, bv0_.z, bv0_.w, bv1_.x, bv1_.y, bv1_.z, bv1_.w};
#pragma unroll
            for (int i = 0; i < 8; i++)
#pragma unroll
                for (int j = 0; j < 8; j++)
                    acc[i][j] = fmaf(a[i], b[j], acc[i][j]);
        }
        if (kk_next < LATENT) {
            *(float4*)&Ws[nxt][wk0][wc0] = w0;
            *(float4*)&Ws[nxt][wk1][wc1] = w1;
            As[nxt][aq0 + 0][ar0] = a0.x; As[nxt][aq0 + 1][ar0] = a0.y;
            As[nxt][aq0 + 2][ar0] = a0.z; As[nxt][aq0 + 3][ar0] = a0.w;
            As[nxt][aq1 + 0][ar1] = a1.x; As[nxt][aq1 + 1][ar1] = a1.y;
            As[nxt][aq1 + 2][ar1] = a1.z; As[nxt][aq1 + 3][ar1] = a1.w;
            __syncthreads();
        }
    }

    // epilogue
    float bs[8];
#pragma unroll
    for (int j = 0; j < 8; j++) bs[j] = bias[tx * 8 + j];
#pragma unroll
    for (int i = 0; i < 8; i++) {
        int r = row0 + ty * 8 + i;
        if (r >= N) continue;
        float rs = rowscale ? rowscale[r] : 1.0f;
        float out[8];
#pragma unroll
        for (int j = 0; j < 8; j++) {
            float c = acc[i][j] + bs[j];
            if (relu) c = fmaxf(c, 0.0f);
            out[j] = c * rs;
        }
        *(float4*)&C[r * LATENT + tx * 8]     = make_float4(out[0], out[1], out[2], out[3]);
        *(float4*)&C[r * LATENT + tx * 8 + 4] = make_float4(out[4], out[5], out[6], out[7]);
    }
}

// ---------------- scatter: agg[recv] += x2[send] via vectorized red ----------------
__global__ void scatter_kernel(const int* __restrict__ senders,
                               const int* __restrict__ receivers) {
    long long idx = (long long)blockIdx.x * blockDim.x + threadIdx.x;
    if (idx >= (long long)N_EDGES * 32) return;
    int e = (int)(idx >> 5);
    int g = (int)(idx & 31);
    int s = senders[e];
    int r = receivers[e];
    float4 v = *(const float4*)&g_x2[s * LATENT + g * 4];
    float* dst = &g_agg[r * LATENT + g * 4];
    asm volatile("red.global.v4.f32.add [%0], {%1, %2, %3, %4};"
                 :: "l"(dst), "f"(v.x), "f"(v.y), "f"(v.z), "f"(v.w)
                 : "memory");
}

// ---------------- skip + layernorm (warp per node), in-place on g_h ----------------
__global__ void ln_kernel(const float* __restrict__ scale,
                          const float* __restrict__ bias) {
    int gid  = blockIdx.x * blockDim.x + threadIdx.x;
    int n    = gid >> 5;
    int lane = gid & 31;
    if (n >= N_NODES) return;
    float ir = g_invr[n];
    float4 hv = *(const float4*)&g_h[n * LATENT + lane * 4];
    float4 av = *(const float4*)&g_agg[n * LATENT + lane * 4];
    float v0 = hv.x + av.x * ir;
    float v1 = hv.y + av.y * ir;
    float v2 = hv.z + av.z * ir;
    float v3 = hv.w + av.w * ir;
    float sum = v0 + v1 + v2 + v3;
    float sq  = v0 * v0 + v1 * v1 + v2 * v2 + v3 * v3;
#pragma unroll
    for (int o = 16; o > 0; o >>= 1) {
        sum += __shfl_xor_sync(0xFFFFFFFF, sum, o);
        sq  += __shfl_xor_sync(0xFFFFFFFF, sq,  o);
    }
    float mean = sum * (1.0f / LATENT);
    float var  = sq * (1.0f / LATENT) - mean * mean;
    float rstd = rsqrtf(var + 1e-6f);
    float4 sc = *(const float4*)&scale[lane * 4];
    float4 bi = *(const float4*)&bias[lane * 4];
    float4 o4;
    o4.x = (v0 - mean) * rstd * sc.x + bi.x;
    o4.y = (v1 - mean) * rstd * sc.y + bi.y;
    o4.z = (v2 - mean) * rstd * sc.z + bi.z;
    o4.w = (v3 - mean) * rstd * sc.w + bi.w;
    *(float4*)&g_h[n * LATENT + lane * 4] = o4;
}

// ---------------- decode: out = h @ W_dec + b_dec (warp per node) ----------------
__global__ void decode_kernel(const float* __restrict__ Wd,
                              const float* __restrict__ bd,
                              float* __restrict__ out) {
    int gid  = blockIdx.x * blockDim.x + threadIdx.x;
    int n    = gid >> 5;
    int lane = gid & 31;
    if (n >= N_NODES) return;
    float4 hv = *(const float4*)&g_h[n * LATENT + lane * 4];
    float h[4] = {hv.x, hv.y, hv.z, hv.w};
    float acc[IN_FEAT];
#pragma unroll
    for (int o = 0; o < IN_FEAT; o++) acc[o] = 0.0f;
#pragma unroll
    for (int q = 0; q < 4; q++) {
        int k = lane * 4 + q;
#pragma unroll
        for (int o = 0; o < IN_FEAT; o++)
            acc[o] = fmaf(h[q], Wd[k * IN_FEAT + o], acc[o]);
    }
#pragma unroll
    for (int o = 0; o < IN_FEAT; o++) {
#pragma unroll
        for (int off = 16; off > 0; off >>= 1)
            acc[o] += __shfl_xor_sync(0xFFFFFFFF, acc[o], off);
    }
    if (lane < IN_FEAT)
        out[n * IN_FEAT + lane] = acc[lane] + bd[lane];
}

// ---------------- host launch ----------------
extern "C" void kernel_launch(void* const* d_in, const int* in_sizes, int n_in,
                              void* d_out, int out_size) {
    const float* nodes     = (const float*)d_in[0];
    const int*   senders   = (const int*)  d_in[1];
    const int*   receivers = (const int*)  d_in[2];
    const float* W_embed   = (const float*)d_in[3];
    const float* b_embed   = (const float*)d_in[4];
    const float* mlp_W     = (const float*)d_in[5];   // [3,2,128,128]
    const float* mlp_b     = (const float*)d_in[6];   // [3,2,128]
    const float* ln_scale  = (const float*)d_in[7];   // [3,128]
    const float* ln_bias   = (const float*)d_in[8];   // [3,128]
    const float* W_dec     = (const float*)d_in[9];   // [128,7]
    const float* b_dec     = (const float*)d_in[10];  // [7]
    float* out = (float*)d_out;

    void *p_h, *p_x1, *p_x2, *p_agg, *p_degs, *p_degr, *p_invs, *p_invr;
    cudaGetSymbolAddress(&p_h,    g_h);
    cudaGetSymbolAddress(&p_x1,   g_x1);
    cudaGetSymbolAddress(&p_x2,   g_x2);
    cudaGetSymbolAddress(&p_agg,  g_agg);
    cudaGetSymbolAddress(&p_degs, g_degs);
    cudaGetSymbolAddress(&p_degr, g_degr);
    cudaGetSymbolAddress(&p_invs, g_invs);
    cudaGetSymbolAddress(&p_invr, g_invr);

    // degrees + normalization
    cudaMemsetAsync(p_degs, 0, N_NODES * sizeof(float), 0);
    cudaMemsetAsync(p_degr, 0, N_NODES * sizeof(float), 0);
    degree_kernel<<<(N_EDGES + 255) / 256, 256>>>(senders, receivers);
    invsqrt_kernel<<<(N_NODES + 255) / 256, 256>>>();

    // embed
    embed_kernel<<<(N_NODES * LATENT + 255) / 256, 256>>>(nodes, W_embed, b_embed);

    const int gemm_grid = (N_NODES + BM - 1) / BM;
    const long long sc_threads = (long long)N_EDGES * 32;
    const int sc_grid = (int)((sc_threads + 255) / 256);
    const int ln_grid = (N_NODES * 32 + 255) / 256;

    for (int step = 0; step < STEPS; step++) {
        const float* W0 = mlp_W + ((size_t)step * 2 + 0) * LATENT * LATENT;
        const float* W1 = mlp_W + ((size_t)step * 2 + 1) * LATENT * LATENT;
        const float* b0 = mlp_b + ((size_t)step * 2 + 0) * LATENT;
        const float* b1 = mlp_b + ((size_t)step * 2 + 1) * LATENT;

        gemm128_kernel<<<gemm_grid, 256>>>((const float*)p_h, W0, b0, nullptr,
                                           (float*)p_x1, N_NODES, 1);
        gemm128_kernel<<<gemm_grid, 256>>>((const float*)p_x1, W1, b1, (const float*)p_invs,
                                           (float*)p_x2, N_NODES, 1);
        cudaMemsetAsync(p_agg, 0, (size_t)N_NODES * LATENT * sizeof(float), 0);
        scatter_kernel<<<sc_grid, 256>>>(senders, receivers);
        ln_kernel<<<ln_grid, 256>>>(ln_scale + step * LATENT, ln_bias + step * LATENT);
    }

    decode_kernel<<<ln_grid, 256>>>(W_dec, b_dec, out);
}